// round 2
// baseline (speedup 1.0000x reference)
#include <cuda_runtime.h>
#include <math.h>

#define NF    32
#define NB    2048
#define NK    64
#define NH    64
#define PAIRS 496
#define PPAD  512
#define TILE_P 64
#define NTILES 8
#define VV_STRIDE 68   // 64 + 4 pad: keeps float4 alignment, de-conflicts banks

__global__ __launch_bounds__(256, 2)
void afm_kernel(const int*   __restrict__ x,      // [F, B]
                const float* __restrict__ emb_v,  // [VOCAB, K]
                const float* __restrict__ at_w,   // [K, H]
                const float* __restrict__ at_b,   // [H]
                const float* __restrict__ at_h,   // [H]
                const float* __restrict__ pvec,   // [K]
                const float* __restrict__ w0,     // scalar
                const float* __restrict__ w1,     // [VOCAB]
                float*       __restrict__ out)    // [B]
{
    __shared__ float sW[NK * NH];                 // 16384 B
    __shared__ float sV[NF * NK];                 //  8192 B
    __shared__ float sVV[TILE_P * VV_STRIDE];     // 17408 B
    __shared__ float sScore[TILE_P];
    __shared__ float sB[NH], sAH[NH], sP[NK];
    __shared__ unsigned char sI[PPAD], sJ[PPAD];
    __shared__ float sPooled[4][NK];
    __shared__ float sFm1;
    __shared__ float sRed[2];

    const int tid = threadIdx.x;
    const int b   = blockIdx.x;

    // ---- load at_w into shared (coalesced float4) ----
    {
        const float4* src = (const float4*)at_w;
        float4*       dst = (float4*)sW;
        #pragma unroll
        for (int i = tid; i < NK * NH / 4; i += 256) dst[i] = src[i];
    }
    if (tid < NH) { sB[tid] = at_b[tid]; sAH[tid] = at_h[tid]; sP[tid] = pvec[tid]; }

    // ---- pair (i,j) table for p in [0, PPAD) ----
    for (int p = tid; p < PPAD; p += 256) {
        int pp = (p < PAIRS) ? p : 0;
        int i = 0, off = 0;
        while (pp >= off + (NF - 1 - i)) { off += NF - 1 - i; i++; }
        sI[p] = (unsigned char)i;
        sJ[p] = (unsigned char)(i + 1 + pp - off);
    }

    // ---- gather embeddings: V[f][k] ----
    for (int idx = tid; idx < NF * (NK / 4); idx += 256) {
        int f = idx >> 4, q = idx & 15;
        int row = __ldg(&x[f * NB + b]);
        ((float4*)sV)[f * 16 + q] = __ldg(&((const float4*)emb_v)[row * 16 + q]);
    }

    // ---- first-order FM term ----
    if (tid < NF) {
        int row = __ldg(&x[tid * NB + b]);
        float v = __ldg(&w1[row]);
        #pragma unroll
        for (int off = 16; off >= 1; off >>= 1)
            v += __shfl_xor_sync(0xffffffffu, v, off);
        if (tid == 0) sFm1 = v + __ldg(w0);
    }
    __syncthreads();

    const int tx = tid & 15;        // h-tile  (4 cols each)
    const int ty = tid >> 4;        // p-tile  (4 rows each)
    const int kb = tid & 63;        // k index for build/pooled phases
    const int pg = tid >> 6;        // pair group (0..3)

    float pooledReg = 0.f;

    for (int t = 0; t < NTILES; t++) {
        // ---- build VV tile (zero-padded beyond PAIRS) ----
        #pragma unroll
        for (int r = 0; r < 16; r++) {
            int pl    = pg * 16 + r;
            int pglob = t * TILE_P + pl;
            float v = 0.f;
            if (pglob < PAIRS)
                v = sV[sI[pglob] * NK + kb] * sV[sJ[pglob] * NK + kb];
            sVV[pl * VV_STRIDE + kb] = v;
        }
        __syncthreads();

        // ---- GEMM: hid[64p, 64h] = VV @ W, 4x4 register tile per thread ----
        float acc[4][4];
        #pragma unroll
        for (int r = 0; r < 4; r++)
            #pragma unroll
            for (int c = 0; c < 4; c++) acc[r][c] = 0.f;

        #pragma unroll 4
        for (int k = 0; k < NK; k += 4) {
            float av[4][4], bv[4][4];
            #pragma unroll
            for (int r = 0; r < 4; r++)
                *(float4*)av[r] = *(const float4*)&sVV[(4 * ty + r) * VV_STRIDE + k];
            #pragma unroll
            for (int q = 0; q < 4; q++)
                *(float4*)bv[q] = *(const float4*)&sW[(k + q) * NH + 4 * tx];
            #pragma unroll
            for (int r = 0; r < 4; r++)
                #pragma unroll
                for (int c = 0; c < 4; c++)
                    #pragma unroll
                    for (int q = 0; q < 4; q++)
                        acc[r][c] = fmaf(av[r][q], bv[q][c], acc[r][c]);
        }

        // ---- per-pair score: relu(hid + b) . at_h, reduced over h ----
        #pragma unroll
        for (int r = 0; r < 4; r++) {
            float s = 0.f;
            #pragma unroll
            for (int c = 0; c < 4; c++) {
                int h = 4 * tx + c;
                float hv = acc[r][c] + sB[h];
                hv = hv > 0.f ? hv : 0.f;
                s = fmaf(hv, sAH[h], s);
            }
            #pragma unroll
            for (int off = 8; off >= 1; off >>= 1)
                s += __shfl_xor_sync(0xffffffffu, s, off);
            if (tx == 0) sScore[4 * ty + r] = s;
        }
        __syncthreads();

        // ---- pooled[k] += sum_p score[p] * VV[p][k] ----
        #pragma unroll
        for (int r = 0; r < 16; r++) {
            int pl = pg * 16 + r;
            pooledReg = fmaf(sScore[pl], sVV[pl * VV_STRIDE + kb], pooledReg);
        }
        __syncthreads();   // before next tile overwrites sVV
    }

    // ---- final reduction: at_fm = pooled . p ; logit ; sigmoid ----
    sPooled[pg][kb] = pooledReg;
    __syncthreads();

    if (tid < NK) {
        float v = (sPooled[0][tid] + sPooled[1][tid] +
                   sPooled[2][tid] + sPooled[3][tid]) * sP[tid];
        #pragma unroll
        for (int off = 16; off >= 1; off >>= 1)
            v += __shfl_xor_sync(0xffffffffu, v, off);
        if ((tid & 31) == 0) sRed[tid >> 5] = v;
    }
    __syncthreads();

    if (tid == 0) {
        float logit = sRed[0] + sRed[1] + sFm1;
        out[b] = 1.f / (1.f + expf(-logit));
    }
}

extern "C" void kernel_launch(void* const* d_in, const int* in_sizes, int n_in,
                              void* d_out, int out_size) {
    const int*   x     = (const int*)  d_in[0];
    const float* emb_v = (const float*)d_in[1];
    const float* at_w  = (const float*)d_in[2];
    const float* at_b  = (const float*)d_in[3];
    const float* at_h  = (const float*)d_in[4];
    const float* pvec  = (const float*)d_in[5];
    const float* w0    = (const float*)d_in[6];
    const float* w1    = (const float*)d_in[7];
    float* out = (float*)d_out;

    afm_kernel<<<NB, 256>>>(x, emb_v, at_w, at_b, at_h, pvec, w0, w1, out);
}

// round 4
// speedup vs baseline: 2.9111x; 2.9111x over previous
#include <cuda_runtime.h>
#include <math.h>
#include <stdint.h>

#define NF    32
#define NB    2048
#define NK    64
#define NH    64
#define PAIRS 496
#define VSTR  68     // sV row stride in floats (keeps float4 align, spreads banks)

__device__ __forceinline__ uint32_t f2tf32(float f) {
    uint32_t u;
    asm("cvt.rna.tf32.f32 %0, %1;" : "=r"(u) : "f"(f));
    return u;
}

__device__ __forceinline__ void mma_tf32(float& d0, float& d1, float& d2, float& d3,
                                         uint32_t a0, uint32_t a1, uint32_t a2, uint32_t a3,
                                         uint32_t b0, uint32_t b1) {
    asm volatile(
        "mma.sync.aligned.m16n8k8.row.col.f32.tf32.tf32.f32 "
        "{%0,%1,%2,%3}, {%4,%5,%6,%7}, {%8,%9}, {%0,%1,%2,%3};"
        : "+f"(d0), "+f"(d1), "+f"(d2), "+f"(d3)
        : "r"(a0), "r"(a1), "r"(a2), "r"(a3), "r"(b0), "r"(b1));
}

__global__ __launch_bounds__(256, 2)
void afm_mma_kernel(const int*   __restrict__ x,      // [F, B]
                    const float* __restrict__ emb_v,  // [VOCAB, K]
                    const float* __restrict__ at_w,   // [K, H]
                    const float* __restrict__ at_b,   // [H]
                    const float* __restrict__ at_h,   // [H]
                    const float* __restrict__ pvec,   // [K]
                    const float* __restrict__ w0,     // scalar
                    const float* __restrict__ w1,     // [VOCAB]
                    float*       __restrict__ out)    // [B]
{
    __shared__ float  sV[NF * VSTR];          //  8704 B gathered embeddings
    __shared__ uint2  sWf[64 * 32];           // 16384 B W fragments [kt*8+nt][lane]
    __shared__ float4 sBA4[32];               //   512 B {b[h0],ah[h0],b[h1],ah[h1]} per (nt,tig)
    __shared__ unsigned char sI[512], sJ[512];
    __shared__ float  sPool[8][NK];           //  2048 B per-warp pooled
    __shared__ float  sFm1, sRed[2];

    const int tid = threadIdx.x;
    const int b   = blockIdx.x;

    // ---- pair (i,j) table ----
    for (int p = tid; p < 512; p += 256) {
        int pp = (p < PAIRS) ? p : 0;
        int i = 0, off = 0;
        while (pp >= off + (NF - 1 - i)) { off += NF - 1 - i; i++; }
        sI[p] = (unsigned char)i;
        sJ[p] = (unsigned char)(i + 1 + pp - off);
    }

    // ---- W fragments (tf32): b0=W[8kt+tig][8nt+gid], b1=W[8kt+tig+4][...] ----
    for (int idx = tid; idx < 2048; idx += 256) {
        int tile = idx >> 5, ln = idx & 31;
        int kt = tile >> 3, nt = tile & 7;
        int tg = ln & 3, gd = ln >> 2;
        int k0 = kt * 8 + tg, h = nt * 8 + gd;
        uint2 v;
        v.x = f2tf32(__ldg(&at_w[k0 * NH + h]));
        v.y = f2tf32(__ldg(&at_w[(k0 + 4) * NH + h]));
        sWf[tile * 32 + ln] = v;
    }

    // ---- bias/at_h fragment table ----
    if (tid < 32) {
        int nt = tid >> 2, tg = tid & 3;
        int h0 = nt * 8 + 2 * tg;
        sBA4[tid] = make_float4(__ldg(&at_b[h0]),     __ldg(&at_h[h0]),
                                __ldg(&at_b[h0 + 1]), __ldg(&at_h[h0 + 1]));
    }

    // ---- gather embeddings ----
    for (int idx = tid; idx < NF * (NK / 4); idx += 256) {
        int f = idx >> 4, q = idx & 15;
        int row = __ldg(&x[f * NB + b]);
        *(float4*)&sV[f * VSTR + q * 4] = __ldg(&((const float4*)emb_v)[row * 16 + q]);
    }

    // ---- first-order FM ----
    if (tid < NF) {
        int row = __ldg(&x[tid * NB + b]);
        float v = __ldg(&w1[row]);
        #pragma unroll
        for (int off = 16; off >= 1; off >>= 1)
            v += __shfl_xor_sync(0xffffffffu, v, off);
        if (tid == 0) sFm1 = v + __ldg(w0);
    }
    __syncthreads();

    const int w    = tid >> 5;
    const int lane = tid & 31;
    const int gid  = lane >> 2;   // fragment group id (row / col-n)
    const int tig  = lane & 3;    // thread-in-group (k / col pair)

    float pooled[16];
    #pragma unroll
    for (int s = 0; s < 16; s++) pooled[s] = 0.f;

    for (int t = 0; t < 4; t++) {
        // pairs owned by this thread: rows gid and gid+8 of the warp's 16-pair strip
        const int p1 = t * 128 + w * 16 + gid;
        const int p2 = p1 + 8;
        const bool ok1 = (p1 < PAIRS);
        const bool ok2 = (p2 < PAIRS);
        const int i1 = sI[p1] * VSTR, j1 = sJ[p1] * VSTR;
        const int i2 = sI[p2] * VSTR, j2 = sJ[p2] * VSTR;

        // ---- build A fragments (VV products, tf32) straight into registers ----
        uint32_t af[8][4];
        #pragma unroll
        for (int kt = 0; kt < 8; kt++) {
            int k0 = kt * 8 + tig;
            float a0 = ok1 ? sV[i1 + k0]     * sV[j1 + k0]     : 0.f;
            float a1 = ok2 ? sV[i2 + k0]     * sV[j2 + k0]     : 0.f;
            float a2 = ok1 ? sV[i1 + k0 + 4] * sV[j1 + k0 + 4] : 0.f;
            float a3 = ok2 ? sV[i2 + k0 + 4] * sV[j2 + k0 + 4] : 0.f;
            af[kt][0] = f2tf32(a0);
            af[kt][1] = f2tf32(a1);
            af[kt][2] = f2tf32(a2);
            af[kt][3] = f2tf32(a3);
        }

        // ---- GEMM + fused epilogue: score = sum_h relu(hid+b)*ah ----
        float s1 = 0.f, s2 = 0.f;
        #pragma unroll
        for (int ntp = 0; ntp < 4; ntp++) {
            float dA0 = 0.f, dA1 = 0.f, dA2 = 0.f, dA3 = 0.f;   // n-tile 2*ntp
            float dB0 = 0.f, dB1 = 0.f, dB2 = 0.f, dB3 = 0.f;   // n-tile 2*ntp+1
            #pragma unroll
            for (int kt = 0; kt < 8; kt++) {
                uint2 bfA = sWf[(kt * 8 + ntp * 2    ) * 32 + lane];
                uint2 bfB = sWf[(kt * 8 + ntp * 2 + 1) * 32 + lane];
                mma_tf32(dA0, dA1, dA2, dA3, af[kt][0], af[kt][1], af[kt][2], af[kt][3], bfA.x, bfA.y);
                mma_tf32(dB0, dB1, dB2, dB3, af[kt][0], af[kt][1], af[kt][2], af[kt][3], bfB.x, bfB.y);
            }
            float4 baA = sBA4[(ntp * 2)     * 4 + tig];
            float4 baB = sBA4[(ntp * 2 + 1) * 4 + tig];
            s1 += fmaxf(dA0 + baA.x, 0.f) * baA.y + fmaxf(dA1 + baA.z, 0.f) * baA.w;
            s2 += fmaxf(dA2 + baA.x, 0.f) * baA.y + fmaxf(dA3 + baA.z, 0.f) * baA.w;
            s1 += fmaxf(dB0 + baB.x, 0.f) * baB.y + fmaxf(dB1 + baB.z, 0.f) * baB.w;
            s2 += fmaxf(dB2 + baB.x, 0.f) * baB.y + fmaxf(dB3 + baB.z, 0.f) * baB.w;
        }
        // reduce partial scores over the 4 lanes of each group (full butterfly)
        s1 += __shfl_xor_sync(0xffffffffu, s1, 1);
        s1 += __shfl_xor_sync(0xffffffffu, s1, 2);
        s2 += __shfl_xor_sync(0xffffffffu, s2, 1);
        s2 += __shfl_xor_sync(0xffffffffu, s2, 2);

        // ---- pooling from the same A registers: pooled[k] += score * VV ----
        #pragma unroll
        for (int kt = 0; kt < 8; kt++) {
            pooled[2 * kt]     = fmaf(s1, __uint_as_float(af[kt][0]),
                                 fmaf(s2, __uint_as_float(af[kt][1]), pooled[2 * kt]));
            pooled[2 * kt + 1] = fmaf(s1, __uint_as_float(af[kt][2]),
                                 fmaf(s2, __uint_as_float(af[kt][3]), pooled[2 * kt + 1]));
        }
    }

    // ---- reduce pooled across the 8 groups (gid) within the warp ----
    #pragma unroll
    for (int s = 0; s < 16; s++) {
        pooled[s] += __shfl_xor_sync(0xffffffffu, pooled[s], 4);
        pooled[s] += __shfl_xor_sync(0xffffffffu, pooled[s], 8);
        pooled[s] += __shfl_xor_sync(0xffffffffu, pooled[s], 16);
    }
    if (gid == 0) {   // lanes 0..3 (lane == tig) hold k = 8kt+tig, 8kt+4+tig
        #pragma unroll
        for (int kt = 0; kt < 8; kt++) {
            sPool[w][kt * 8 + tig]     = pooled[2 * kt];
            sPool[w][kt * 8 + 4 + tig] = pooled[2 * kt + 1];
        }
    }
    __syncthreads();

    // ---- final: at_fm = (sum_w pooled) . p ; logit ; sigmoid ----
    if (tid < NK) {
        float v = 0.f;
        #pragma unroll
        for (int g = 0; g < 8; g++) v += sPool[g][tid];
        v *= __ldg(&pvec[tid]);
        #pragma unroll
        for (int off = 16; off >= 1; off >>= 1)
            v += __shfl_xor_sync(0xffffffffu, v, off);
        if ((tid & 31) == 0) sRed[tid >> 5] = v;
    }
    __syncthreads();

    if (tid == 0) {
        float logit = sRed[0] + sRed[1] + sFm1;
        out[b] = 1.f / (1.f + expf(-logit));
    }
}

extern "C" void kernel_launch(void* const* d_in, const int* in_sizes, int n_in,
                              void* d_out, int out_size) {
    const int*   x     = (const int*)  d_in[0];
    const float* emb_v = (const float*)d_in[1];
    const float* at_w  = (const float*)d_in[2];
    const float* at_b  = (const float*)d_in[3];
    const float* at_h  = (const float*)d_in[4];
    const float* pvec  = (const float*)d_in[5];
    const float* w0    = (const float*)d_in[6];
    const float* w1    = (const float*)d_in[7];
    float* out = (float*)d_out;

    afm_mma_kernel<<<NB, 256>>>(x, emb_v, at_w, at_b, at_h, pvec, w0, w1, out);
}

// round 5
// speedup vs baseline: 3.1109x; 1.0686x over previous
#include <cuda_runtime.h>
#include <cuda_bf16.h>
#include <math.h>
#include <stdint.h>

#define NF    32
#define NB    2048
#define NK    64
#define NH    64
#define PAIRS 496
#define VSTR  68     // sV row stride in floats

// Pre-packed W fragment table: [ks(4)][nt(8)][lane(32)] -> uint2 {b0,b1}
__device__ uint2 g_wfrag[4 * 8 * 32];

__device__ __forceinline__ uint32_t pack_bf16x2(float lo, float hi) {
    __nv_bfloat162 h = __floats2bfloat162_rn(lo, hi);
    return *reinterpret_cast<uint32_t*>(&h);
}
__device__ __forceinline__ float2 unpack_bf16x2(uint32_t u) {
    __nv_bfloat162 h = *reinterpret_cast<__nv_bfloat162*>(&u);
    return __bfloat1622float2(h);
}

__device__ __forceinline__ void mma_bf16(float& d0, float& d1, float& d2, float& d3,
                                         uint32_t a0, uint32_t a1, uint32_t a2, uint32_t a3,
                                         uint32_t b0, uint32_t b1) {
    asm volatile(
        "mma.sync.aligned.m16n8k16.row.col.f32.bf16.bf16.f32 "
        "{%0,%1,%2,%3}, {%4,%5,%6,%7}, {%8,%9}, {%0,%1,%2,%3};"
        : "+f"(d0), "+f"(d1), "+f"(d2), "+f"(d3)
        : "r"(a0), "r"(a1), "r"(a2), "r"(a3), "r"(b0), "r"(b1));
}

// ---- pre-kernel: pack W into mma B-fragment layout (bf16) ----
// b0 = {W[k0][h], W[k0+1][h]}, b1 = {W[k0+8][h], W[k0+9][h]},
// k0 = ks*16 + 2*tig, h = nt*8 + gid.
__global__ void wfrag_build(const float* __restrict__ at_w) {
    int idx  = blockIdx.x * 256 + threadIdx.x;   // 0..1023
    int lane = idx & 31;
    int tile = idx >> 5;          // 0..31
    int ks = tile >> 3, nt = tile & 7;
    int tig = lane & 3, gid = lane >> 2;
    int k0 = ks * 16 + 2 * tig;
    int h  = nt * 8 + gid;
    uint2 v;
    v.x = pack_bf16x2(at_w[k0 * NH + h],       at_w[(k0 + 1) * NH + h]);
    v.y = pack_bf16x2(at_w[(k0 + 8) * NH + h], at_w[(k0 + 9) * NH + h]);
    g_wfrag[idx] = v;
}

__global__ __launch_bounds__(256, 2)
void afm_mma_kernel(const int*   __restrict__ x,      // [F, B]
                    const float* __restrict__ emb_v,  // [VOCAB, K]
                    const float* __restrict__ at_b,   // [H]
                    const float* __restrict__ at_h,   // [H]
                    const float* __restrict__ pvec,   // [K]
                    const float* __restrict__ w0,     // scalar
                    const float* __restrict__ w1,     // [VOCAB]
                    float*       __restrict__ out)    // [B]
{
    __shared__ float  sV[NF * VSTR];          // 8704 B gathered embeddings
    __shared__ float4 sBA4[32];               // {b[h0],ah[h0],b[h1],ah[h1]} per (nt,tig)
    __shared__ unsigned char sI[512], sJ[512];
    __shared__ float  sPool[8][NK];
    __shared__ float  sFm1, sRed[2];

    const int tid = threadIdx.x;
    const int b   = blockIdx.x;
    const int w    = tid >> 5;
    const int lane = tid & 31;
    const int gid  = lane >> 2;
    const int tig  = lane & 3;

    // ---- W fragments: 32 coalesced LDG.64, held in registers for the whole kernel ----
    uint2 Wb[4][8];
    #pragma unroll
    for (int ks = 0; ks < 4; ks++)
        #pragma unroll
        for (int nt = 0; nt < 8; nt++)
            Wb[ks][nt] = __ldg(&g_wfrag[(ks * 8 + nt) * 32 + lane]);

    // ---- pair (i,j) table ----
    for (int p = tid; p < 512; p += 256) {
        int pp = (p < PAIRS) ? p : 0;
        int i = 0, off = 0;
        while (pp >= off + (NF - 1 - i)) { off += NF - 1 - i; i++; }
        sI[p] = (unsigned char)i;
        sJ[p] = (unsigned char)(i + 1 + pp - off);
    }

    // ---- bias/at_h fragment table ----
    if (tid < 32) {
        int nt = tid >> 2, tg = tid & 3;
        int h0 = nt * 8 + 2 * tg;
        sBA4[tid] = make_float4(__ldg(&at_b[h0]),     __ldg(&at_h[h0]),
                                __ldg(&at_b[h0 + 1]), __ldg(&at_h[h0 + 1]));
    }

    // ---- gather embeddings ----
    for (int idx = tid; idx < NF * (NK / 4); idx += 256) {
        int f = idx >> 4, q = idx & 15;
        int row = __ldg(&x[f * NB + b]);
        *(float4*)&sV[f * VSTR + q * 4] = __ldg(&((const float4*)emb_v)[row * 16 + q]);
    }

    // ---- first-order FM ----
    if (tid < NF) {
        int row = __ldg(&x[tid * NB + b]);
        float v = __ldg(&w1[row]);
        #pragma unroll
        for (int off = 16; off >= 1; off >>= 1)
            v += __shfl_xor_sync(0xffffffffu, v, off);
        if (tid == 0) sFm1 = v + __ldg(w0);
    }
    __syncthreads();

    float pooled[16];
    #pragma unroll
    for (int s = 0; s < 16; s++) pooled[s] = 0.f;

    #pragma unroll
    for (int t = 0; t < 4; t++) {
        const int p1 = t * 128 + w * 16 + gid;
        const int p2 = p1 + 8;
        const bool ok1 = (p1 < PAIRS);
        const bool ok2 = (p2 < PAIRS);
        const int i1 = sI[p1] * VSTR, j1 = sJ[p1] * VSTR;
        const int i2 = sI[p2] * VSTR, j2 = sJ[p2] * VSTR;

        // ---- A fragments: VV products (bf16x2), k-pairs via float2 loads ----
        uint32_t af[4][4];   // [ks][{p1lo,p2lo,p1hi,p2hi}]
        #pragma unroll
        for (int ks = 0; ks < 4; ks++) {
            int k0 = ks * 16 + 2 * tig;
            int k1 = k0 + 8;
            float2 r0 = make_float2(0.f, 0.f), r1 = r0, r2 = r0, r3 = r0;
            if (ok1) {
                float2 vi = *(const float2*)&sV[i1 + k0];
                float2 vj = *(const float2*)&sV[j1 + k0];
                r0 = make_float2(vi.x * vj.x, vi.y * vj.y);
                vi = *(const float2*)&sV[i1 + k1];
                vj = *(const float2*)&sV[j1 + k1];
                r2 = make_float2(vi.x * vj.x, vi.y * vj.y);
            }
            if (ok2) {
                float2 vi = *(const float2*)&sV[i2 + k0];
                float2 vj = *(const float2*)&sV[j2 + k0];
                r1 = make_float2(vi.x * vj.x, vi.y * vj.y);
                vi = *(const float2*)&sV[i2 + k1];
                vj = *(const float2*)&sV[j2 + k1];
                r3 = make_float2(vi.x * vj.x, vi.y * vj.y);
            }
            af[ks][0] = pack_bf16x2(r0.x, r0.y);
            af[ks][1] = pack_bf16x2(r1.x, r1.y);
            af[ks][2] = pack_bf16x2(r2.x, r2.y);
            af[ks][3] = pack_bf16x2(r3.x, r3.y);
        }

        // ---- GEMM (W from registers) + fused score epilogue ----
        float s1 = 0.f, s2 = 0.f;
        #pragma unroll
        for (int nt = 0; nt < 8; nt++) {
            float d0 = 0.f, d1 = 0.f, d2 = 0.f, d3 = 0.f;
            #pragma unroll
            for (int ks = 0; ks < 4; ks++)
                mma_bf16(d0, d1, d2, d3,
                         af[ks][0], af[ks][1], af[ks][2], af[ks][3],
                         Wb[ks][nt].x, Wb[ks][nt].y);
            float4 ba = sBA4[nt * 4 + tig];   // broadcast (4 distinct addrs)
            s1 += fmaxf(d0 + ba.x, 0.f) * ba.y + fmaxf(d1 + ba.z, 0.f) * ba.w;
            s2 += fmaxf(d2 + ba.x, 0.f) * ba.y + fmaxf(d3 + ba.z, 0.f) * ba.w;
        }
        // reduce scores over the 4 tig lanes
        s1 += __shfl_xor_sync(0xffffffffu, s1, 1);
        s1 += __shfl_xor_sync(0xffffffffu, s1, 2);
        s2 += __shfl_xor_sync(0xffffffffu, s2, 1);
        s2 += __shfl_xor_sync(0xffffffffu, s2, 2);

        // ---- pooling from the same A registers ----
        #pragma unroll
        for (int ks = 0; ks < 4; ks++) {
            float2 v;
            v = unpack_bf16x2(af[ks][0]);
            pooled[ks * 4 + 0] = fmaf(s1, v.x, pooled[ks * 4 + 0]);
            pooled[ks * 4 + 1] = fmaf(s1, v.y, pooled[ks * 4 + 1]);
            v = unpack_bf16x2(af[ks][1]);
            pooled[ks * 4 + 0] = fmaf(s2, v.x, pooled[ks * 4 + 0]);
            pooled[ks * 4 + 1] = fmaf(s2, v.y, pooled[ks * 4 + 1]);
            v = unpack_bf16x2(af[ks][2]);
            pooled[ks * 4 + 2] = fmaf(s1, v.x, pooled[ks * 4 + 2]);
            pooled[ks * 4 + 3] = fmaf(s1, v.y, pooled[ks * 4 + 3]);
            v = unpack_bf16x2(af[ks][3]);
            pooled[ks * 4 + 2] = fmaf(s2, v.x, pooled[ks * 4 + 2]);
            pooled[ks * 4 + 3] = fmaf(s2, v.y, pooled[ks * 4 + 3]);
        }
    }

    // ---- reduce pooled across gid lanes ----
    #pragma unroll
    for (int s = 0; s < 16; s++) {
        pooled[s] += __shfl_xor_sync(0xffffffffu, pooled[s], 4);
        pooled[s] += __shfl_xor_sync(0xffffffffu, pooled[s], 8);
        pooled[s] += __shfl_xor_sync(0xffffffffu, pooled[s], 16);
    }
    if (gid == 0) {   // lanes 0..3: k = ks*16 + 2tig (+1, +8, +9)
        #pragma unroll
        for (int ks = 0; ks < 4; ks++) {
            int k0 = ks * 16 + 2 * tig;
            sPool[w][k0]     = pooled[ks * 4 + 0];
            sPool[w][k0 + 1] = pooled[ks * 4 + 1];
            sPool[w][k0 + 8] = pooled[ks * 4 + 2];
            sPool[w][k0 + 9] = pooled[ks * 4 + 3];
        }
    }
    __syncthreads();

    // ---- final: at_fm = (sum_w pooled) . p ; logit ; sigmoid ----
    if (tid < NK) {
        float v = 0.f;
        #pragma unroll
        for (int g = 0; g < 8; g++) v += sPool[g][tid];
        v *= __ldg(&pvec[tid]);
        #pragma unroll
        for (int off = 16; off >= 1; off >>= 1)
            v += __shfl_xor_sync(0xffffffffu, v, off);
        if ((tid & 31) == 0) sRed[tid >> 5] = v;
    }
    __syncthreads();

    if (tid == 0) {
        float logit = sRed[0] + sRed[1] + sFm1;
        out[b] = 1.f / (1.f + expf(-logit));
    }
}

extern "C" void kernel_launch(void* const* d_in, const int* in_sizes, int n_in,
                              void* d_out, int out_size) {
    const int*   x     = (const int*)  d_in[0];
    const float* emb_v = (const float*)d_in[1];
    const float* at_w  = (const float*)d_in[2];
    const float* at_b  = (const float*)d_in[3];
    const float* at_h  = (const float*)d_in[4];
    const float* pvec  = (const float*)d_in[5];
    const float* w0    = (const float*)d_in[6];
    const float* w1    = (const float*)d_in[7];
    float* out = (float*)d_out;

    wfrag_build<<<4, 256>>>(at_w);
    afm_mma_kernel<<<NB, 256>>>(x, emb_v, at_b, at_h, pvec, w0, w1, out);
}

// round 6
// speedup vs baseline: 3.2442x; 1.0429x over previous
#include <cuda_runtime.h>
#include <cuda_bf16.h>
#include <math.h>
#include <stdint.h>

#define NF    32
#define NB    2048
#define NK    64
#define NH    64
#define PAIRS 496
#define VSTR  68     // sV row stride in floats (float4-aligned, 4-bank row shift)
#define ZROW  32     // zero row index for padded pairs

// Pre-packed W fragment table (permuted-k layout): [ks(4)][nt(8)][lane(32)]
__device__ uint2 g_wfrag[4 * 8 * 32];

__device__ __forceinline__ uint32_t pack_bf16x2(float lo, float hi) {
    __nv_bfloat162 h = __floats2bfloat162_rn(lo, hi);
    return *reinterpret_cast<uint32_t*>(&h);
}
__device__ __forceinline__ float2 unpack_bf16x2(uint32_t u) {
    __nv_bfloat162 h = *reinterpret_cast<__nv_bfloat162*>(&u);
    return __bfloat1622float2(h);
}

__device__ __forceinline__ void mma_bf16(float& d0, float& d1, float& d2, float& d3,
                                         uint32_t a0, uint32_t a1, uint32_t a2, uint32_t a3,
                                         uint32_t b0, uint32_t b1) {
    asm volatile(
        "mma.sync.aligned.m16n8k16.row.col.f32.bf16.bf16.f32 "
        "{%0,%1,%2,%3}, {%4,%5,%6,%7}, {%8,%9}, {%0,%1,%2,%3};"
        : "+f"(d0), "+f"(d1), "+f"(d2), "+f"(d3)
        : "r"(a0), "r"(a1), "r"(a2), "r"(a3), "r"(b0), "r"(b1));
}

// ---- pre-kernel: pack W with the k-permutation ----
// mma slot {2tig,2tig+1} <- logical k = ks*16 + 4tig + {0,1}
// mma slot {2tig+8,2tig+9} <- logical k = ks*16 + 4tig + {2,3}
__global__ void wfrag_build(const float* __restrict__ at_w) {
    int idx  = blockIdx.x * 256 + threadIdx.x;   // 0..1023
    int lane = idx & 31;
    int tile = idx >> 5;
    int ks = tile >> 3, nt = tile & 7;
    int tig = lane & 3, gid = lane >> 2;
    int lk = ks * 16 + 4 * tig;
    int h  = nt * 8 + gid;
    uint2 v;
    v.x = pack_bf16x2(at_w[lk * NH + h],       at_w[(lk + 1) * NH + h]);
    v.y = pack_bf16x2(at_w[(lk + 2) * NH + h], at_w[(lk + 3) * NH + h]);
    g_wfrag[idx] = v;
}

__global__ __launch_bounds__(256, 2)
void afm_mma_kernel(const int*   __restrict__ x,      // [F, B]
                    const float* __restrict__ emb_v,  // [VOCAB, K]
                    const float* __restrict__ at_b,   // [H]
                    const float* __restrict__ at_h,   // [H]
                    const float* __restrict__ pvec,   // [K]
                    const float* __restrict__ w0,     // scalar
                    const float* __restrict__ w1,     // [VOCAB]
                    float*       __restrict__ out)    // [B]
{
    __shared__ float  sV[(NF + 1) * VSTR];    // +1 zero row for padded pairs
    __shared__ float4 sBA4[32];               // {b[h0],ah[h0],b[h1],ah[h1]} per (nt,tig)
    __shared__ unsigned char sI[512], sJ[512];
    __shared__ float  sPool[8][NK];
    __shared__ float  sFm1, sRed[2];

    const int tid = threadIdx.x;
    const int b   = blockIdx.x;
    const int w    = tid >> 5;
    const int lane = tid & 31;
    const int gid  = lane >> 2;
    const int tig  = lane & 3;

    // ---- W fragments: held in registers for the whole kernel ----
    uint2 Wb[4][8];
    #pragma unroll
    for (int ks = 0; ks < 4; ks++)
        #pragma unroll
        for (int nt = 0; nt < 8; nt++)
            Wb[ks][nt] = __ldg(&g_wfrag[(ks * 8 + nt) * 32 + lane]);

    // ---- pair (i,j) table; padded pairs -> zero row ----
    for (int p = tid; p < 512; p += 256) {
        if (p < PAIRS) {
            int pp = p, i = 0, off = 0;
            while (pp >= off + (NF - 1 - i)) { off += NF - 1 - i; i++; }
            sI[p] = (unsigned char)i;
            sJ[p] = (unsigned char)(i + 1 + pp - off);
        } else {
            sI[p] = ZROW; sJ[p] = ZROW;
        }
    }

    // ---- zero row ----
    if (tid < NK) sV[ZROW * VSTR + tid] = 0.f;

    // ---- bias/at_h fragment table ----
    if (tid < 32) {
        int nt = tid >> 2, tg = tid & 3;
        int h0 = nt * 8 + 2 * tg;
        sBA4[tid] = make_float4(__ldg(&at_b[h0]),     __ldg(&at_h[h0]),
                                __ldg(&at_b[h0 + 1]), __ldg(&at_h[h0 + 1]));
    }

    // ---- gather embeddings ----
    for (int idx = tid; idx < NF * (NK / 4); idx += 256) {
        int f = idx >> 4, q = idx & 15;
        int row = __ldg(&x[f * NB + b]);
        *(float4*)&sV[f * VSTR + q * 4] = __ldg(&((const float4*)emb_v)[row * 16 + q]);
    }

    // ---- first-order FM ----
    if (tid < NF) {
        int row = __ldg(&x[tid * NB + b]);
        float v = __ldg(&w1[row]);
        #pragma unroll
        for (int off = 16; off >= 1; off >>= 1)
            v += __shfl_xor_sync(0xffffffffu, v, off);
        if (tid == 0) sFm1 = v + __ldg(w0);
    }
    __syncthreads();

    float pooled[16];
    #pragma unroll
    for (int s = 0; s < 16; s++) pooled[s] = 0.f;

    const int kbase = 4 * tig;   // logical k offset within each 16-block

    #pragma unroll
    for (int t = 0; t < 4; t++) {
        const int p1 = t * 128 + w * 16 + gid;
        const int p2 = p1 + 8;
        const float* ri1 = &sV[sI[p1] * VSTR + kbase];
        const float* rj1 = &sV[sJ[p1] * VSTR + kbase];
        const float* ri2 = &sV[sI[p2] * VSTR + kbase];
        const float* rj2 = &sV[sJ[p2] * VSTR + kbase];

        // ---- A fragments: one float4 per row per kstep (16 LDS.128/tile) ----
        uint32_t af[4][4];   // [ks][a0..a3]
        #pragma unroll
        for (int ks = 0; ks < 4; ks++) {
            const int ko = ks * 16;
            float4 vi = *(const float4*)(ri1 + ko);
            float4 vj = *(const float4*)(rj1 + ko);
            float4 a1v = make_float4(vi.x * vj.x, vi.y * vj.y, vi.z * vj.z, vi.w * vj.w);
            vi = *(const float4*)(ri2 + ko);
            vj = *(const float4*)(rj2 + ko);
            float4 a2v = make_float4(vi.x * vj.x, vi.y * vj.y, vi.z * vj.z, vi.w * vj.w);
            af[ks][0] = pack_bf16x2(a1v.x, a1v.y);
            af[ks][2] = pack_bf16x2(a1v.z, a1v.w);
            af[ks][1] = pack_bf16x2(a2v.x, a2v.y);
            af[ks][3] = pack_bf16x2(a2v.z, a2v.w);
        }

        // ---- GEMM (W in registers) + fused score epilogue ----
        float s1 = 0.f, s2 = 0.f;
        #pragma unroll
        for (int nt = 0; nt < 8; nt++) {
            float d0 = 0.f, d1 = 0.f, d2 = 0.f, d3 = 0.f;
            #pragma unroll
            for (int ks = 0; ks < 4; ks++)
                mma_bf16(d0, d1, d2, d3,
                         af[ks][0], af[ks][1], af[ks][2], af[ks][3],
                         Wb[ks][nt].x, Wb[ks][nt].y);
            float4 ba = sBA4[nt * 4 + tig];   // broadcast LDS.128
            s1 += fmaxf(d0 + ba.x, 0.f) * ba.y + fmaxf(d1 + ba.z, 0.f) * ba.w;
            s2 += fmaxf(d2 + ba.x, 0.f) * ba.y + fmaxf(d3 + ba.z, 0.f) * ba.w;
        }
        s1 += __shfl_xor_sync(0xffffffffu, s1, 1);
        s1 += __shfl_xor_sync(0xffffffffu, s1, 2);
        s2 += __shfl_xor_sync(0xffffffffu, s2, 1);
        s2 += __shfl_xor_sync(0xffffffffu, s2, 2);

        // ---- pooling from the same A registers (logical k contiguous) ----
        #pragma unroll
        for (int ks = 0; ks < 4; ks++) {
            float2 v;
            v = unpack_bf16x2(af[ks][0]);
            pooled[ks * 4 + 0] = fmaf(s1, v.x, pooled[ks * 4 + 0]);
            pooled[ks * 4 + 1] = fmaf(s1, v.y, pooled[ks * 4 + 1]);
            v = unpack_bf16x2(af[ks][2]);
            pooled[ks * 4 + 2] = fmaf(s1, v.x, pooled[ks * 4 + 2]);
            pooled[ks * 4 + 3] = fmaf(s1, v.y, pooled[ks * 4 + 3]);
            v = unpack_bf16x2(af[ks][1]);
            pooled[ks * 4 + 0] = fmaf(s2, v.x, pooled[ks * 4 + 0]);
            pooled[ks * 4 + 1] = fmaf(s2, v.y, pooled[ks * 4 + 1]);
            v = unpack_bf16x2(af[ks][3]);
            pooled[ks * 4 + 2] = fmaf(s2, v.x, pooled[ks * 4 + 2]);
            pooled[ks * 4 + 3] = fmaf(s2, v.y, pooled[ks * 4 + 3]);
        }
    }

    // ---- reduce pooled across gid lanes ----
    #pragma unroll
    for (int s = 0; s < 16; s++) {
        pooled[s] += __shfl_xor_sync(0xffffffffu, pooled[s], 4);
        pooled[s] += __shfl_xor_sync(0xffffffffu, pooled[s], 8);
        pooled[s] += __shfl_xor_sync(0xffffffffu, pooled[s], 16);
    }
    if (gid == 0) {   // lanes 0..3: logical k = ks*16 + 4tig + {0..3} -> float4 store
        #pragma unroll
        for (int ks = 0; ks < 4; ks++)
            *(float4*)&sPool[w][ks * 16 + 4 * tig] =
                make_float4(pooled[ks * 4 + 0], pooled[ks * 4 + 1],
                            pooled[ks * 4 + 2], pooled[ks * 4 + 3]);
    }
    __syncthreads();

    // ---- final: at_fm = (sum_w pooled) . p ; logit ; sigmoid ----
    if (tid < NK) {
        float v = 0.f;
        #pragma unroll
        for (int g = 0; g < 8; g++) v += sPool[g][tid];
        v *= __ldg(&pvec[tid]);
        #pragma unroll
        for (int off = 16; off >= 1; off >>= 1)
            v += __shfl_xor_sync(0xffffffffu, v, off);
        if ((tid & 31) == 0) sRed[tid >> 5] = v;
    }
    __syncthreads();

    if (tid == 0) {
        float logit = sRed[0] + sRed[1] + sFm1;
        out[b] = 1.f / (1.f + expf(-logit));
    }
}

extern "C" void kernel_launch(void* const* d_in, const int* in_sizes, int n_in,
                              void* d_out, int out_size) {
    const int*   x     = (const int*)  d_in[0];
    const float* emb_v = (const float*)d_in[1];
    const float* at_w  = (const float*)d_in[2];
    const float* at_b  = (const float*)d_in[3];
    const float* at_h  = (const float*)d_in[4];
    const float* pvec  = (const float*)d_in[5];
    const float* w0    = (const float*)d_in[6];
    const float* w1    = (const float*)d_in[7];
    float* out = (float*)d_out;

    wfrag_build<<<4, 256>>>(at_w);
    afm_mma_kernel<<<NB, 256>>>(x, emb_v, at_b, at_h, pvec, w0, w1, out);
}